// round 16
// baseline (speedup 1.0000x reference)
#include <cuda_runtime.h>
#include <cuda_bf16.h>

// IIR lfilter (order-8, 9 taps), DF2T, chunked parallelization.
// x: (64, 64, 8192) fp32 -> y = clip(lfilter(x, A, B), -1, 1)
//
// R15: R14 (validated best, 82.6us) + double-buffered emit tiles so each
// 16-sample tile needs ONE __syncthreads() instead of two:
//   [LDG next | compute xs[p]->ys[p] | stage->xs[1-p] | BAR | gather ys[p]]
// Manual unroll-by-2 keeps smem buffer addresses static. Warm phase (register
// FIR, fused G table, WARM=192) and NCH=16 layout unchanged from R14.

#define T_LEN   8192
#define M_SEQ   4096
#define NCH     16         // chunks per sequence
#define CHUNK   512        // T_LEN / NCH
#define WARM    192        // FIR taps (0.95^192 ~ 5e-5 transient)
#define TT      16         // time-tile
#define STRIDE  130        // SMEM row stride (conflict-free under this lane map)

// One DF2T step. State z0..z7; unclamped y feeds the recurrence.
#define IIR_STEP(xv, yout)                                       \
    do {                                                         \
        float _iir_y = fmaf(b0, (xv), z0);                       \
        z0 = fmaf(-a1, _iir_y, fmaf(b1, (xv), z1));              \
        z1 = fmaf(-a2, _iir_y, fmaf(b2, (xv), z2));              \
        z2 = fmaf(-a3, _iir_y, fmaf(b3, (xv), z3));              \
        z3 = fmaf(-a4, _iir_y, fmaf(b4, (xv), z4));              \
        z4 = fmaf(-a5, _iir_y, fmaf(b5, (xv), z5));              \
        z5 = fmaf(-a6, _iir_y, fmaf(b6, (xv), z6));              \
        z6 = fmaf(-a7, _iir_y, fmaf(b7, (xv), z7));              \
        z7 = fmaf(-a8, _iir_y, b8 * (xv));                       \
        (yout) = _iir_y;                                         \
    } while (0)

#define LOAD_TILE(buf, tbase)                                        \
    do {                                                             \
        _Pragma("unroll")                                            \
        for (int i = 0; i < 4; i++)                                  \
            (buf)[i] = *reinterpret_cast<const float4*>(             \
                xbase + (size_t)i * 32 * T_LEN + (tbase));           \
    } while (0)

#define STAGE_TILE(dst, buf)                                         \
    do {                                                             \
        _Pragma("unroll")                                            \
        for (int i = 0; i < 4; i++) {                                \
            const int _r = rl + 32 * i;                              \
            (dst)[(col + 0) * STRIDE + _r] = (buf)[i].x;             \
            (dst)[(col + 1) * STRIDE + _r] = (buf)[i].y;             \
            (dst)[(col + 2) * STRIDE + _r] = (buf)[i].z;             \
            (dst)[(col + 3) * STRIDE + _r] = (buf)[i].w;             \
        }                                                            \
    } while (0)

// One emit tile with single barrier:
//   prefetch(tnext) ; compute xsrd->ysw ; stage pf->xsnx ; BAR ; gather ysw
#define EMIT_TILE(xsrd, ysw, xsnx, tcur, tnext)                      \
    do {                                                             \
        LOAD_TILE(pf, (tnext));                                      \
        _Pragma("unroll")                                            \
        for (int tt = 0; tt < TT; tt++) {                            \
            const float xv = (xsrd)[tt * STRIDE + tid];              \
            float yo;                                                \
            IIR_STEP(xv, yo);                                        \
            (ysw)[tt * STRIDE + tid] = fminf(fmaxf(yo, -1.0f), 1.0f);\
        }                                                            \
        STAGE_TILE((xsnx), pf);                                      \
        __syncthreads();                                             \
        _Pragma("unroll")                                            \
        for (int i = 0; i < 4; i++) {                                \
            const int _r = rl + 32 * i;                              \
            float4 v;                                                \
            v.x = (ysw)[(col + 0) * STRIDE + _r];                    \
            v.y = (ysw)[(col + 1) * STRIDE + _r];                    \
            v.z = (ysw)[(col + 2) * STRIDE + _r];                    \
            v.w = (ysw)[(col + 3) * STRIDE + _r];                    \
            *reinterpret_cast<float4*>(                              \
                ybase + (size_t)i * 32 * T_LEN + (tcur)) = v;        \
        }                                                            \
    } while (0)

__global__ __launch_bounds__(128, 4)
void iir_fused_kernel(const float* __restrict__ x,
                      const float* __restrict__ Ag,
                      const float* __restrict__ Bg,
                      float* __restrict__ y)
{
    __shared__ float  xs0[TT * STRIDE], xs1[TT * STRIDE];
    __shared__ float  ys0[TT * STRIDE], ys1[TT * STRIDE];
    __shared__ float4 gs03[WARM];        // G(d) states z0..z3
    __shared__ float4 gs47[WARM];        // G(d) states z4..z7

    const int tid   = threadIdx.x;                 // 0..127 = local sequence
    const int c     = blockIdx.x >> 5;             // chunk index 0..15 (block-uniform)
    const int mbase = (blockIdx.x & 31) << 7;      // 128 sequences per block

    // Lane map for tile I/O: thread -> (row base rl, time column col).
    const int rl  = tid >> 2;           // 0..31; rows rl + 32*i
    const int cj  = tid & 3;            // 0..3
    const int col = cj << 2;            // 0,4,8,12

    const float* xbase = x + (size_t)(mbase + rl) * T_LEN + col;
    float*       ybase = y + (size_t)(mbase + rl) * T_LEN + col;

    const int tout = c * CHUNK;
    const int tend = tout + CHUNK;

    float z0 = 0.f, z1 = 0.f, z2 = 0.f, z3 = 0.f,
          z4 = 0.f, z5 = 0.f, z6 = 0.f, z7 = 0.f;

    float4 pf[4];

    if (c > 0) {
        // ---- G table: impulse response of DF2T state, computed per block ----
        if (tid == 0) {
            const float ginv = 1.0f / Ag[0];
            float ga[9], gb[9];
#pragma unroll
            for (int i = 0; i < 9; i++) { ga[i] = Ag[i] * ginv; gb[i] = Bg[i] * ginv; }
            float gz[8];
            const float gy0 = gb[0];                       // impulse step
#pragma unroll
            for (int i = 0; i < 8; i++) gz[i] = gb[i + 1] - ga[i + 1] * gy0;
            gs03[0] = make_float4(gz[0], gz[1], gz[2], gz[3]);
            gs47[0] = make_float4(gz[4], gz[5], gz[6], gz[7]);
            for (int d = 1; d < WARM; d++) {
                const float yv = gz[0];                    // zero-input step
#pragma unroll
                for (int i = 0; i < 7; i++) gz[i] = gz[i + 1] - ga[i + 1] * yv;
                gz[7] = -ga[8] * yv;
                gs03[d] = make_float4(gz[0], gz[1], gz[2], gz[3]);
                gs47[d] = make_float4(gz[4], gz[5], gz[6], gz[7]);
            }
        }
        __syncthreads();

        // ---- Warm phase: register FIR over the loader's own data ----
        float acc[4][8];
#pragma unroll
        for (int i = 0; i < 4; i++)
#pragma unroll
            for (int s = 0; s < 8; s++) acc[i][s] = 0.f;

        const int tstart = tout - WARM;
        for (int t = tstart; t < tout; t += TT) {
            LOAD_TILE(pf, t);
            const int dbase = tout - 1 - t - col;          // per-thread
#pragma unroll
            for (int k = 0; k < 4; k++) {
                const float4 g0 = gs03[dbase - k];         // 4 addrs/warp: 1 wf
                const float4 g1 = gs47[dbase - k];
#pragma unroll
                for (int i = 0; i < 4; i++) {
                    const float xv = reinterpret_cast<const float*>(&pf[i])[k];
                    acc[i][0] = fmaf(g0.x, xv, acc[i][0]);
                    acc[i][1] = fmaf(g0.y, xv, acc[i][1]);
                    acc[i][2] = fmaf(g0.z, xv, acc[i][2]);
                    acc[i][3] = fmaf(g0.w, xv, acc[i][3]);
                    acc[i][4] = fmaf(g1.x, xv, acc[i][4]);
                    acc[i][5] = fmaf(g1.y, xv, acc[i][5]);
                    acc[i][6] = fmaf(g1.z, xv, acc[i][6]);
                    acc[i][7] = fmaf(g1.w, xv, acc[i][7]);
                }
            }
        }

        // Butterfly all-reduce across the 4 col-lanes (lanes xor 1, xor 2).
#pragma unroll
        for (int i = 0; i < 4; i++)
#pragma unroll
            for (int s = 0; s < 8; s++) {
                acc[i][s] += __shfl_xor_sync(0xFFFFFFFFu, acc[i][s], 1);
                acc[i][s] += __shfl_xor_sync(0xFFFFFFFFu, acc[i][s], 2);
            }

        // Prefetch first emit tile while the exchange settles.
        LOAD_TILE(pf, tout);

        // Exchange: states -> owner threads via ys0 scratch (ys0[s][row]).
        if (cj == 0) {
#pragma unroll
            for (int i = 0; i < 4; i++)
#pragma unroll
                for (int s = 0; s < 8; s++)
                    ys0[s * STRIDE + (rl + 32 * i)] = acc[i][s];
        }
        __syncthreads();
        z0 = ys0[0 * STRIDE + tid];
        z1 = ys0[1 * STRIDE + tid];
        z2 = ys0[2 * STRIDE + tid];
        z3 = ys0[3 * STRIDE + tid];
        z4 = ys0[4 * STRIDE + tid];
        z5 = ys0[5 * STRIDE + tid];
        z6 = ys0[6 * STRIDE + tid];
        z7 = ys0[7 * STRIDE + tid];

        STAGE_TILE(xs0, pf);        // first emit tile
        __syncthreads();            // xs0 staged; z reads done before ys0 reuse
    } else {
        // c == 0: zero state, stage tile at t=0.
        LOAD_TILE(pf, 0);
        STAGE_TILE(xs0, pf);
        __syncthreads();
    }

    // Coefficients (normalized by A[0]) — loaded after warm to cut warm-phase
    // register pressure.
    const float inv = 1.0f / __ldg(&Ag[0]);
    const float a1 = __ldg(&Ag[1]) * inv;
    const float a2 = __ldg(&Ag[2]) * inv;
    const float a3 = __ldg(&Ag[3]) * inv;
    const float a4 = __ldg(&Ag[4]) * inv;
    const float a5 = __ldg(&Ag[5]) * inv;
    const float a6 = __ldg(&Ag[6]) * inv;
    const float a7 = __ldg(&Ag[7]) * inv;
    const float a8 = __ldg(&Ag[8]) * inv;
    const float b0 = __ldg(&Bg[0]) * inv;
    const float b1 = __ldg(&Bg[1]) * inv;
    const float b2 = __ldg(&Bg[2]) * inv;
    const float b3 = __ldg(&Bg[3]) * inv;
    const float b4 = __ldg(&Bg[4]) * inv;
    const float b5 = __ldg(&Bg[5]) * inv;
    const float b6 = __ldg(&Bg[6]) * inv;
    const float b7 = __ldg(&Bg[7]) * inv;
    const float b8 = __ldg(&Bg[8]) * inv;

    // ======= Emit phase: IIR over [tout, tend), 1 barrier per tile =======
    for (int t = tout; t < tend; t += 2 * TT) {
        const int tn1 = t + TT;                                   // always < tend+TT
        const int tn2 = (t + 2 * TT < tend) ? (t + 2 * TT) : tout; // clamp
        EMIT_TILE(xs0, ys0, xs1, t,   tn1);
        EMIT_TILE(xs1, ys1, xs0, tn1, tn2);
    }
}

extern "C" void kernel_launch(void* const* d_in, const int* in_sizes, int n_in,
                              void* d_out, int out_size)
{
    const float* x = (const float*)d_in[0];
    const float* A = (const float*)d_in[1];
    const float* B = (const float*)d_in[2];
    float*       y = (float*)d_out;

    // 32 seq-blocks (128 sequences each) x 16 chunks = 512 blocks of 128.
    iir_fused_kernel<<<(M_SEQ / 128) * NCH, 128>>>(x, A, B, y);
}

// round 17
// speedup vs baseline: 1.3837x; 1.3837x over previous
#include <cuda_runtime.h>
#include <cuda_bf16.h>

// IIR lfilter (order-8, 9 taps), DF2T, chunked parallelization.
// x: (64, 64, 8192) fp32 -> y = clip(lfilter(x, A, B), -1, 1)
//
// R16: revert R15's single-barrier double-buffer (measured regression,
// issue 31%). Combine the two independently validated bests:
//  - warm phase: R14's register FIR + fused G table (WARM=192, NCH=16)
//  - emit phase: R8's TT=32 tiling (issue 44.8% measured at this occupancy
//    vs 38.9% for TT=16), classic 2-barrier pattern, STRIDE=129 lane map.

#define T_LEN   8192
#define M_SEQ   4096
#define NCH     16         // chunks per sequence
#define CHUNK   512        // T_LEN / NCH
#define WARM    192        // FIR taps (0.95^192 ~ 5e-5 transient)
#define WTT     16         // warm-phase time step (pf[4] lane map)
#define TT      32         // emit time-tile (R8-validated)
#define STRIDE  129        // emit SMEM row stride (conflict-free, R5/R8 map)

// One DF2T step. State z0..z7; unclamped y feeds the recurrence.
#define IIR_STEP(xv, yout)                                       \
    do {                                                         \
        float _iir_y = fmaf(b0, (xv), z0);                       \
        z0 = fmaf(-a1, _iir_y, fmaf(b1, (xv), z1));              \
        z1 = fmaf(-a2, _iir_y, fmaf(b2, (xv), z2));              \
        z2 = fmaf(-a3, _iir_y, fmaf(b3, (xv), z3));              \
        z3 = fmaf(-a4, _iir_y, fmaf(b4, (xv), z4));              \
        z4 = fmaf(-a5, _iir_y, fmaf(b5, (xv), z5));              \
        z5 = fmaf(-a6, _iir_y, fmaf(b6, (xv), z6));              \
        z6 = fmaf(-a7, _iir_y, fmaf(b7, (xv), z7));              \
        z7 = fmaf(-a8, _iir_y, b8 * (xv));                       \
        (yout) = _iir_y;                                         \
    } while (0)

__global__ __launch_bounds__(128, 4)
void iir_fused_kernel(const float* __restrict__ x,
                      const float* __restrict__ Ag,
                      const float* __restrict__ Bg,
                      float* __restrict__ y)
{
    __shared__ float  xs[TT * STRIDE];   // [time][seq] transpose tile (emit)
    __shared__ float  ys[TT * STRIDE];   // output tile; reused as state scratch
    __shared__ float4 gs03[WARM];        // G(d) states z0..z3
    __shared__ float4 gs47[WARM];        // G(d) states z4..z7

    const int tid   = threadIdx.x;                 // 0..127 = local sequence
    const int c     = blockIdx.x >> 5;             // chunk index 0..15 (block-uniform)
    const int mbase = (blockIdx.x & 31) << 7;      // 128 sequences per block

    // Warm-phase lane map (R14): 32 row groups x 4 time cols.
    const int rl4  = tid >> 2;          // 0..31; rows rl4 + 32*i, i<4
    const int cj4  = tid & 3;           // 0..3
    const int col4 = cj4 << 2;          // 0,4,8,12

    // Emit-phase lane map (R8): 16 row groups x 8 time cols.
    const int rl8  = tid >> 3;          // 0..15; rows rl8 + 16*i, i<8
    const int col8 = (tid & 7) << 2;    // 0,4,...,28

    const float* xb4 = x + (size_t)(mbase + rl4) * T_LEN + col4;
    const float* xb8 = x + (size_t)(mbase + rl8) * T_LEN + col8;
    float*       yb8 = y + (size_t)(mbase + rl8) * T_LEN + col8;

    const int tout = c * CHUNK;
    const int tend = tout + CHUNK;

    float z0 = 0.f, z1 = 0.f, z2 = 0.f, z3 = 0.f,
          z4 = 0.f, z5 = 0.f, z6 = 0.f, z7 = 0.f;

    float4 pf8[8];

    if (c > 0) {
        // ---- G table: impulse response of DF2T state, computed per block ----
        if (tid == 0) {
            const float ginv = 1.0f / Ag[0];
            float ga[9], gb[9];
#pragma unroll
            for (int i = 0; i < 9; i++) { ga[i] = Ag[i] * ginv; gb[i] = Bg[i] * ginv; }
            float gz[8];
            const float gy0 = gb[0];                       // impulse step
#pragma unroll
            for (int i = 0; i < 8; i++) gz[i] = gb[i + 1] - ga[i + 1] * gy0;
            gs03[0] = make_float4(gz[0], gz[1], gz[2], gz[3]);
            gs47[0] = make_float4(gz[4], gz[5], gz[6], gz[7]);
            for (int d = 1; d < WARM; d++) {
                const float yv = gz[0];                    // zero-input step
#pragma unroll
                for (int i = 0; i < 7; i++) gz[i] = gz[i + 1] - ga[i + 1] * yv;
                gz[7] = -ga[8] * yv;
                gs03[d] = make_float4(gz[0], gz[1], gz[2], gz[3]);
                gs47[d] = make_float4(gz[4], gz[5], gz[6], gz[7]);
            }
        }
        __syncthreads();

        // ---- Warm phase: register FIR over the loader's own data (R14) ----
        float acc[4][8];
#pragma unroll
        for (int i = 0; i < 4; i++)
#pragma unroll
            for (int s = 0; s < 8; s++) acc[i][s] = 0.f;

        const int tstart = tout - WARM;
        for (int t = tstart; t < tout; t += WTT) {
            float4 pw[4];
#pragma unroll
            for (int i = 0; i < 4; i++)
                pw[i] = *reinterpret_cast<const float4*>(xb4 + (size_t)i * 32 * T_LEN + t);

            const int dbase = tout - 1 - t - col4;         // per-thread
#pragma unroll
            for (int k = 0; k < 4; k++) {
                const float4 g0 = gs03[dbase - k];         // 4 addrs/warp: 1 wf
                const float4 g1 = gs47[dbase - k];
#pragma unroll
                for (int i = 0; i < 4; i++) {
                    const float xv = reinterpret_cast<const float*>(&pw[i])[k];
                    acc[i][0] = fmaf(g0.x, xv, acc[i][0]);
                    acc[i][1] = fmaf(g0.y, xv, acc[i][1]);
                    acc[i][2] = fmaf(g0.z, xv, acc[i][2]);
                    acc[i][3] = fmaf(g0.w, xv, acc[i][3]);
                    acc[i][4] = fmaf(g1.x, xv, acc[i][4]);
                    acc[i][5] = fmaf(g1.y, xv, acc[i][5]);
                    acc[i][6] = fmaf(g1.z, xv, acc[i][6]);
                    acc[i][7] = fmaf(g1.w, xv, acc[i][7]);
                }
            }
        }

        // Butterfly all-reduce across the 4 col-lanes (lanes xor 1, xor 2).
#pragma unroll
        for (int i = 0; i < 4; i++)
#pragma unroll
            for (int s = 0; s < 8; s++) {
                acc[i][s] += __shfl_xor_sync(0xFFFFFFFFu, acc[i][s], 1);
                acc[i][s] += __shfl_xor_sync(0xFFFFFFFFu, acc[i][s], 2);
            }

        // Prefetch first emit tile while the exchange settles.
#pragma unroll
        for (int i = 0; i < 8; i++)
            pf8[i] = *reinterpret_cast<const float4*>(xb8 + (size_t)i * 16 * T_LEN + tout);

        // Exchange: states -> owner threads via ys scratch (ys[s][row]).
        if (cj4 == 0) {
#pragma unroll
            for (int i = 0; i < 4; i++)
#pragma unroll
                for (int s = 0; s < 8; s++)
                    ys[s * STRIDE + (rl4 + 32 * i)] = acc[i][s];
        }
        __syncthreads();
        z0 = ys[0 * STRIDE + tid];
        z1 = ys[1 * STRIDE + tid];
        z2 = ys[2 * STRIDE + tid];
        z3 = ys[3 * STRIDE + tid];
        z4 = ys[4 * STRIDE + tid];
        z5 = ys[5 * STRIDE + tid];
        z6 = ys[6 * STRIDE + tid];
        z7 = ys[7 * STRIDE + tid];

        // Stage first emit tile into xs (emit lane map).
#pragma unroll
        for (int i = 0; i < 8; i++) {
            const int r = rl8 + 16 * i;
            xs[(col8 + 0) * STRIDE + r] = pf8[i].x;
            xs[(col8 + 1) * STRIDE + r] = pf8[i].y;
            xs[(col8 + 2) * STRIDE + r] = pf8[i].z;
            xs[(col8 + 3) * STRIDE + r] = pf8[i].w;
        }
        __syncthreads();   // xs staged; all z reads done before ys is rewritten
    } else {
        // c == 0: zero state, stage tile at t=0.
#pragma unroll
        for (int i = 0; i < 8; i++)
            pf8[i] = *reinterpret_cast<const float4*>(xb8 + (size_t)i * 16 * T_LEN);
#pragma unroll
        for (int i = 0; i < 8; i++) {
            const int r = rl8 + 16 * i;
            xs[(col8 + 0) * STRIDE + r] = pf8[i].x;
            xs[(col8 + 1) * STRIDE + r] = pf8[i].y;
            xs[(col8 + 2) * STRIDE + r] = pf8[i].z;
            xs[(col8 + 3) * STRIDE + r] = pf8[i].w;
        }
        __syncthreads();
    }

    // Coefficients (normalized by A[0]).
    const float inv = 1.0f / __ldg(&Ag[0]);
    const float a1 = __ldg(&Ag[1]) * inv;
    const float a2 = __ldg(&Ag[2]) * inv;
    const float a3 = __ldg(&Ag[3]) * inv;
    const float a4 = __ldg(&Ag[4]) * inv;
    const float a5 = __ldg(&Ag[5]) * inv;
    const float a6 = __ldg(&Ag[6]) * inv;
    const float a7 = __ldg(&Ag[7]) * inv;
    const float a8 = __ldg(&Ag[8]) * inv;
    const float b0 = __ldg(&Bg[0]) * inv;
    const float b1 = __ldg(&Bg[1]) * inv;
    const float b2 = __ldg(&Bg[2]) * inv;
    const float b3 = __ldg(&Bg[3]) * inv;
    const float b4 = __ldg(&Bg[4]) * inv;
    const float b5 = __ldg(&Bg[5]) * inv;
    const float b6 = __ldg(&Bg[6]) * inv;
    const float b7 = __ldg(&Bg[7]) * inv;
    const float b8 = __ldg(&Bg[8]) * inv;

    // ===== Emit phase: IIR over [tout, tend), TT=32, 2-barrier pattern =====
    for (int t = tout; t < tend; t += TT) {
        const int tp = (t + TT < tend) ? (t + TT) : tout;   // in-bounds clamp
#pragma unroll
        for (int i = 0; i < 8; i++)
            pf8[i] = *reinterpret_cast<const float4*>(xb8 + (size_t)i * 16 * T_LEN + tp);

#pragma unroll
        for (int tt = 0; tt < TT; tt++) {
            const float xv = xs[tt * STRIDE + tid];
            float yo;
            IIR_STEP(xv, yo);
            ys[tt * STRIDE + tid] = fminf(fmaxf(yo, -1.0f), 1.0f);
        }
        __syncthreads();   // ys complete; xs consumed

        // Coalesced output of this tile.
#pragma unroll
        for (int i = 0; i < 8; i++) {
            const int r = rl8 + 16 * i;
            float4 v;
            v.x = ys[(col8 + 0) * STRIDE + r];
            v.y = ys[(col8 + 1) * STRIDE + r];
            v.z = ys[(col8 + 2) * STRIDE + r];
            v.w = ys[(col8 + 3) * STRIDE + r];
            *reinterpret_cast<float4*>(yb8 + (size_t)i * 16 * T_LEN + t) = v;
        }

        // Stage prefetched tile.
#pragma unroll
        for (int i = 0; i < 8; i++) {
            const int r = rl8 + 16 * i;
            xs[(col8 + 0) * STRIDE + r] = pf8[i].x;
            xs[(col8 + 1) * STRIDE + r] = pf8[i].y;
            xs[(col8 + 2) * STRIDE + r] = pf8[i].z;
            xs[(col8 + 3) * STRIDE + r] = pf8[i].w;
        }
        __syncthreads();
    }
}

extern "C" void kernel_launch(void* const* d_in, const int* in_sizes, int n_in,
                              void* d_out, int out_size)
{
    const float* x = (const float*)d_in[0];
    const float* A = (const float*)d_in[1];
    const float* B = (const float*)d_in[2];
    float*       y = (float*)d_out;

    // 32 seq-blocks (128 sequences each) x 16 chunks = 512 blocks of 128.
    iir_fused_kernel<<<(M_SEQ / 128) * NCH, 128>>>(x, A, B, y);
}